// round 3
// baseline (speedup 1.0000x reference)
#include <cuda_runtime.h>
#include <math.h>
#include <stdint.h>

#define NU 50000
#define NI 30000
#define NE 100000
#define EK 500000
#define EIc 1000000
#define DD 64
#define KD 32

// ---------------- scratch (module globals; no runtime allocation) ----------------
__device__ __align__(16) float g_Qu[NU * DD];
__device__ __align__(16) float g_Kt[NI * DD];
__device__ __align__(16) float g_Vt[NI * DD];
__device__ __align__(16) float g_scores[EIc];
__device__ __align__(16) unsigned g_mkey[NU];
__device__ __align__(16) float g_den[NU];
__device__ __align__(16) float g_cntu[NU];
__device__ __align__(16) float g_s[DD];
__device__ __align__(16) float g_omega[EK];
__device__ __align__(16) float g_segO[NE];
__device__ __align__(16) float g_segE[NE];
__device__ __align__(16) float g_cntH[NE];
__device__ __align__(16) float g_alpha[EK];
__device__ __align__(16) float g_eta[EK];
__device__ __align__(16) float g_eemb[NE * DD];
__device__ __align__(16) float g_eagg[NE * DD];
__device__ __align__(16) float g_uagg[NU * DD];

// ---------------- helpers ----------------
__device__ __forceinline__ unsigned fkey(float f) {
    unsigned b = __float_as_uint(f);
    return (b & 0x80000000u) ? ~b : (b | 0x80000000u);
}
__device__ __forceinline__ float fdecode(unsigned k) {
    unsigned b = (k & 0x80000000u) ? (k ^ 0x80000000u) : ~k;
    return __uint_as_float(b);
}
__device__ __forceinline__ float n2n(float x) {
    if (isnan(x)) return 0.f;
    if (isinf(x)) return (x > 0.f) ? 1e4f : 1e-4f;
    return x;
}
__device__ __forceinline__ void redAdd4(float* p, float4 v) {
    asm volatile("red.global.add.v4.f32 [%0], {%1, %2, %3, %4};"
                 :: "l"(p), "f"(v.x), "f"(v.y), "f"(v.z), "f"(v.w)
                 : "memory");
}
__device__ __forceinline__ float sigmoidf_(float x) { return 1.f / (1.f + expf(-x)); }

// ---------------- kernels ----------------

// O[rows,64] = A[rows,64] @ W[64,64]
__global__ void gemm64_kernel(const float* __restrict__ A, const float* __restrict__ W,
                              float* __restrict__ O, int rows) {
    __shared__ float sW[4096];
    for (int i = threadIdx.x; i < 4096; i += blockDim.x) sW[i] = W[i];
    __syncthreads();
    int idx = blockIdx.x * blockDim.x + threadIdx.x;
    if (idx >= rows * 64) return;
    int r = idx >> 6, c = idx & 63;
    const float* a = A + (r << 6);
    float acc = 0.f;
#pragma unroll
    for (int k = 0; k < 64; k++) acc = fmaf(a[k], sW[(k << 6) + c], acc);
    O[idx] = acc;
}

// warp per interaction edge: score = dot(q,k)/8 * w;  segment max via atomicMax
__global__ void scores_kernel(const float* __restrict__ Qu, const float* __restrict__ Kt,
                              const int* __restrict__ inter, const float* __restrict__ iw,
                              float* __restrict__ scores, unsigned* __restrict__ mkey) {
    int e = blockIdx.x * (blockDim.x >> 5) + (threadIdx.x >> 5);
    if (e >= EIc) return;
    int lane = threadIdx.x & 31;
    int u = inter[e], it = inter[EIc + e];
    const float* q = Qu + u * 64;
    const float* k = Kt + it * 64;
    float p = q[lane] * k[lane] + q[lane + 32] * k[lane + 32];
#pragma unroll
    for (int o = 16; o; o >>= 1) p += __shfl_xor_sync(0xffffffffu, p, o);
    if (lane == 0) {
        float sc = p * 0.125f * iw[e];
        scores[e] = sc;
        atomicMax(&mkey[u], fkey(sc));
    }
}

__global__ void exp_kernel(const int* __restrict__ inter, float* __restrict__ scores,
                           const unsigned* __restrict__ mkey, float* __restrict__ den,
                           float* __restrict__ cntu) {
    int e = blockIdx.x * blockDim.x + threadIdx.x;
    if (e >= EIc) return;
    int u = inter[e];
    float m = fdecode(mkey[u]);
    float ex = expf(scores[e] - m);
    scores[e] = ex;
    atomicAdd(&den[u], ex);
    atomicAdd(&cntu[u], 1.f);
}

// s[d] = sum_e (alpha_e / max(cnt_u,1)) * V[item_e][d]
__global__ void pref_kernel(const float* __restrict__ Vt, const int* __restrict__ inter,
                            const float* __restrict__ exv, const float* __restrict__ den,
                            const float* __restrict__ cntu, float* __restrict__ s) {
    __shared__ float sacc[64];
    if (threadIdx.x < 64) sacc[threadIdx.x] = 0.f;
    __syncthreads();
    int lane = threadIdx.x & 31;
    int nw = gridDim.x * (blockDim.x >> 5);
    float a0 = 0.f, a1 = 0.f;
    for (int e = blockIdx.x * (blockDim.x >> 5) + (threadIdx.x >> 5); e < EIc; e += nw) {
        int u = inter[e], it = inter[EIc + e];
        float coef = exv[e] / den[u] / fmaxf(cntu[u], 1.f);
        const float* v = Vt + it * 64;
        a0 = fmaf(coef, v[lane], a0);
        a1 = fmaf(coef, v[lane + 32], a1);
    }
    atomicAdd(&sacc[lane], a0);
    atomicAdd(&sacc[lane + 32], a1);
    __syncthreads();
    if (threadIdx.x < 64) atomicAdd(&s[threadIdx.x], sacc[threadIdx.x]);
}

// warp per KG edge: fact-semantic MLP + gating router -> omega[e]
__global__ __launch_bounds__(256) void fact_router_kernel(
    const int* __restrict__ eidx, const int* __restrict__ etype,
    const float* __restrict__ entR, const float* __restrict__ entI,
    const float* __restrict__ relR, const float* __restrict__ relI,
    const float* __restrict__ fpW1, const float* __restrict__ fpb1,
    const float* __restrict__ fpW2, const float* __restrict__ fpb2,
    const float* __restrict__ rtW1, const float* __restrict__ rtb1,
    const float* __restrict__ rtW2, const float* __restrict__ rtb2,
    const float* __restrict__ sv, float* __restrict__ omega) {
    extern __shared__ float sm[];
    float* sW1 = sm;             // 12288
    float* sB1 = sW1 + 12288;    // 64
    float* sW2 = sB1 + 64;       // 192
    float* sB2 = sW2 + 192;      // 4
    float* sRW1 = sB2 + 4;       // 4096
    float* sRB1 = sRW1 + 4096;   // 64
    float* sRW2 = sRB1 + 64;     // 4096
    float* sRB2 = sRW2 + 4096;   // 64
    float* sS = sRB2 + 64;       // 64

    for (int i = threadIdx.x; i < 12288; i += blockDim.x) sW1[i] = fpW1[i];
    for (int i = threadIdx.x; i < 4096; i += blockDim.x) { sRW1[i] = rtW1[i]; sRW2[i] = rtW2[i]; }
    for (int i = threadIdx.x; i < 192; i += blockDim.x) sW2[i] = fpW2[i];
    if (threadIdx.x < 64) { sB1[threadIdx.x] = fpb1[threadIdx.x]; sRB1[threadIdx.x] = rtb1[threadIdx.x];
                            sRB2[threadIdx.x] = rtb2[threadIdx.x]; sS[threadIdx.x] = sv[threadIdx.x]; }
    if (threadIdx.x < 3) sB2[threadIdx.x] = fpb2[threadIdx.x];
    __syncthreads();

    int lane = threadIdx.x & 31;
    int nw = gridDim.x * (blockDim.x >> 5);
    const float2* W1v = (const float2*)sW1;
    const float2* RW1v = (const float2*)sRW1;
    const float2* RW2v = (const float2*)sRW2;

    for (int e = blockIdx.x * (blockDim.x >> 5) + (threadIdx.x >> 5); e < EK; e += nw) {
        int hh = eidx[e], tt = eidx[EK + e], rr = etype[e] - 1;
        float f0 = entR[hh * 32 + lane], f1 = entI[hh * 32 + lane];
        float f2 = relR[rr * 32 + lane], f3 = relI[rr * 32 + lane];
        float f4 = entR[tt * 32 + lane], f5 = entI[tt * 32 + lane];
        float fl[6] = {f0, f1, f2, f3, f4, f5};
        float ax = 0.f, ay = 0.f;
#pragma unroll
        for (int b = 0; b < 6; b++) {
            float fb = fl[b];
#pragma unroll
            for (int l0 = 0; l0 < 32; l0++) {
                float fv = __shfl_sync(0xffffffffu, fb, l0);
                float2 wv = W1v[(b * 32 + l0) * 32 + lane];
                ax = fmaf(fv, wv.x, ax);
                ay = fmaf(fv, wv.y, ay);
            }
        }
        float h0 = sigmoidf_(sB1[2 * lane] + ax);
        float h1 = sigmoidf_(sB1[2 * lane + 1] + ay);
        float p0 = h0 * sW2[(2 * lane) * 3 + 0] + h1 * sW2[(2 * lane + 1) * 3 + 0];
        float p1 = h0 * sW2[(2 * lane) * 3 + 1] + h1 * sW2[(2 * lane + 1) * 3 + 1];
        float p2 = h0 * sW2[(2 * lane) * 3 + 2] + h1 * sW2[(2 * lane + 1) * 3 + 2];
#pragma unroll
        for (int o = 16; o; o >>= 1) {
            p0 += __shfl_xor_sync(0xffffffffu, p0, o);
            p1 += __shfl_xor_sync(0xffffffffu, p1, o);
            p2 += __shfl_xor_sync(0xffffffffu, p2, o);
        }
        p0 += sB2[0]; p1 += sB2[1]; p2 += sB2[2];
        float mx = fmaxf(p0, fmaxf(p1, p2));
        float e0 = expf(p0 - mx), e1 = expf(p1 - mx), e2 = expf(p2 - mx);
        float inv = 1.f / (e0 + e1 + e2);
        float w0 = e0 * inv, w1 = e1 * inv, w2 = e2 * inv;
        float fa = w0 * f0 + w1 * f2 + w2 * f4;   // br[lane]
        float fb2 = w0 * f1 + w1 * f3 + w2 * f5;  // bi[lane]

        float gx = 0.f, gy = 0.f;
#pragma unroll
        for (int l0 = 0; l0 < 32; l0++) {
            float fv = __shfl_sync(0xffffffffu, fa, l0);
            float2 wv = RW1v[l0 * 32 + lane];
            gx = fmaf(fv, wv.x, gx);
            gy = fmaf(fv, wv.y, gy);
        }
#pragma unroll
        for (int l0 = 0; l0 < 32; l0++) {
            float fv = __shfl_sync(0xffffffffu, fb2, l0);
            float2 wv = RW1v[(32 + l0) * 32 + lane];
            gx = fmaf(fv, wv.x, gx);
            gy = fmaf(fv, wv.y, gy);
        }
        float g0 = sigmoidf_(sRB1[2 * lane] + gx);
        float g1 = sigmoidf_(sRB1[2 * lane + 1] + gy);

        float aax = 0.f, aay = 0.f;
#pragma unroll
        for (int l0 = 0; l0 < 32; l0++) {
            float gv0 = __shfl_sync(0xffffffffu, g0, l0);
            float gv1 = __shfl_sync(0xffffffffu, g1, l0);
            float2 wv0 = RW2v[(2 * l0) * 32 + lane];
            float2 wv1 = RW2v[(2 * l0 + 1) * 32 + lane];
            aax = fmaf(gv0, wv0.x, fmaf(gv1, wv1.x, aax));
            aay = fmaf(gv0, wv0.y, fmaf(gv1, wv1.y, aay));
        }
        aax += sRB2[2 * lane];
        aay += sRB2[2 * lane + 1];
        float pp = aax * sS[2 * lane] + aay * sS[2 * lane + 1];
#pragma unroll
        for (int o = 16; o; o >>= 1) pp += __shfl_xor_sync(0xffffffffu, pp, o);
        if (lane == 0) omega[e] = pp * 0.125f;
    }
}

__global__ void sego_kernel(const int* __restrict__ eidx, const float* __restrict__ omega,
                            float* __restrict__ segO, float* __restrict__ cntH) {
    int e = blockIdx.x * blockDim.x + threadIdx.x;
    if (e >= EK) return;
    int hh = eidx[e];
    atomicAdd(&segO[hh], omega[e]);
    atomicAdd(&cntH[hh], 1.f);
}

__global__ void alpha_kernel(const int* __restrict__ eidx, const float* __restrict__ omega,
                             const float* __restrict__ segO, float* __restrict__ alpha,
                             float* __restrict__ eta, float* __restrict__ segE) {
    int e = blockIdx.x * blockDim.x + threadIdx.x;
    if (e >= EK) return;
    int hh = eidx[e];
    float a = omega[e] / (segO[hh] + 1e-8f);
    alpha[e] = a;
    float et = (a > 0.2f) ? a : 0.f;
    eta[e] = et;
    if (et != 0.f) atomicAdd(&segE[hh], et);
}

__global__ void eta_kernel(const int* __restrict__ eidx, const float* __restrict__ segE,
                           float* __restrict__ eta) {
    int e = blockIdx.x * blockDim.x + threadIdx.x;
    if (e >= EK) return;
    int hh = eidx[e];
    eta[e] = eta[e] / (segE[hh] + 1e-8f);
}

// half-warp per KG edge, lane handles 4 dims, vector reduction into e_agg
__global__ void kg_scatter_kernel(const int* __restrict__ eidx, const int* __restrict__ etype,
                                  const float* __restrict__ relemb, const float* __restrict__ eemb,
                                  const float* __restrict__ rho, float* __restrict__ eagg) {
    int e = blockIdx.x * (blockDim.x >> 4) + (threadIdx.x >> 4);
    if (e >= EK) return;
    int d0 = (threadIdx.x & 15) << 2;
    int hh = eidx[e], tt = eidx[EK + e], rr = etype[e] - 1;
    float rh = rho[e];
    float4 ev = *(const float4*)(eemb + tt * 64 + d0);
    float4 rv = *(const float4*)(relemb + rr * 64 + d0);
    float4 val = make_float4(ev.x * rv.x * rh, ev.y * rv.y * rh,
                             ev.z * rv.z * rh, ev.w * rv.w * rh);
    redAdd4(eagg + hh * 64 + d0, val);
}

__global__ void ui_scatter_kernel(const int* __restrict__ inter, const float* __restrict__ iw,
                                  const float* __restrict__ eemb, float* __restrict__ uagg) {
    int e = blockIdx.x * (blockDim.x >> 4) + (threadIdx.x >> 4);
    if (e >= EIc) return;
    int d0 = (threadIdx.x & 15) << 2;
    int u = inter[e], it = inter[EIc + e];
    float w = iw[e];
    float4 ev = *(const float4*)(eemb + it * 64 + d0);
    redAdd4(uagg + u * 64 + d0, make_float4(ev.x * w, ev.y * w, ev.z * w, ev.w * w));
}

__global__ void fin_ent_kernel(const float* __restrict__ eagg, const float* __restrict__ cntH,
                               float* __restrict__ eemb, float* __restrict__ outp) {
    int n = blockIdx.x * (blockDim.x >> 5) + (threadIdx.x >> 5);
    if (n >= NE) return;
    int lane = threadIdx.x & 31;
    float inv = 1.f / fmaxf(cntH[n], 1.f);
    float2 v = *(const float2*)(eagg + n * 64 + 2 * lane);
    v.x *= inv; v.y *= inv;
    float ss = v.x * v.x + v.y * v.y;
#pragma unroll
    for (int o = 16; o; o >>= 1) ss += __shfl_xor_sync(0xffffffffu, ss, o);
    float invn = 1.f / fmaxf(sqrtf(ss), 1e-8f);
    float a = n2n(v.x * invn), b = n2n(v.y * invn);
    *(float2*)(eemb + n * 64 + 2 * lane) = make_float2(a, b);
    float2 o2 = *(float2*)(outp + n * 64 + 2 * lane);
    o2.x += a; o2.y += b;
    *(float2*)(outp + n * 64 + 2 * lane) = o2;
}

__global__ void fin_usr_kernel(const float* __restrict__ uagg, float* __restrict__ outp) {
    int n = blockIdx.x * (blockDim.x >> 5) + (threadIdx.x >> 5);
    if (n >= NU) return;
    int lane = threadIdx.x & 31;
    float2 v = *(const float2*)(uagg + n * 64 + 2 * lane);
    float ss = v.x * v.x + v.y * v.y;
#pragma unroll
    for (int o = 16; o; o >>= 1) ss += __shfl_xor_sync(0xffffffffu, ss, o);
    float invn = 1.f / fmaxf(sqrtf(ss), 1e-8f);
    float a = n2n(v.x * invn), b = n2n(v.y * invn);
    float2 o2 = *(float2*)(outp + n * 64 + 2 * lane);
    o2.x += a; o2.y += b;
    *(float2*)(outp + n * 64 + 2 * lane) = o2;
}

// ---------------- host launch ----------------
extern "C" void kernel_launch(void* const* d_in, const int* in_sizes, int n_in,
                              void* d_out, int out_size) {
    const float* user_embed = (const float*)d_in[0];
    const float* item_embed = (const float*)d_in[1];
    const float* Wq = (const float*)d_in[2];
    const float* Wk = (const float*)d_in[3];
    const float* Wv = (const float*)d_in[4];
    const float* ent_real = (const float*)d_in[5];
    const float* ent_imag = (const float*)d_in[6];
    const float* rel_real = (const float*)d_in[7];
    const float* rel_imag = (const float*)d_in[8];
    const float* fp_W1 = (const float*)d_in[9];
    const float* fp_b1 = (const float*)d_in[10];
    const float* fp_W2 = (const float*)d_in[11];
    const float* fp_b2 = (const float*)d_in[12];
    const float* rt_W1 = (const float*)d_in[13];
    const float* rt_b1 = (const float*)d_in[14];
    const float* rt_W2 = (const float*)d_in[15];
    const float* rt_b2 = (const float*)d_in[16];
    const float* relation_emb = (const float*)d_in[17];
    const float* user_emb = (const float*)d_in[18];
    const float* entity_emb = (const float*)d_in[19];
    const float* inter_edge_w = (const float*)d_in[20];
    const int* edge_index = (const int*)d_in[21];
    const int* edge_type = (const int*)d_in[22];
    const int* inter_edge = (const int*)d_in[23];
    float* out = (float*)d_out;

    float *Qu, *Kt, *Vt, *scores, *den, *cntu, *sv, *omega, *segO, *segE, *cntH;
    float *alpha, *eta, *eemb, *eagg, *uagg;
    unsigned* mkey;
    cudaGetSymbolAddress((void**)&Qu, g_Qu);
    cudaGetSymbolAddress((void**)&Kt, g_Kt);
    cudaGetSymbolAddress((void**)&Vt, g_Vt);
    cudaGetSymbolAddress((void**)&scores, g_scores);
    cudaGetSymbolAddress((void**)&mkey, g_mkey);
    cudaGetSymbolAddress((void**)&den, g_den);
    cudaGetSymbolAddress((void**)&cntu, g_cntu);
    cudaGetSymbolAddress((void**)&sv, g_s);
    cudaGetSymbolAddress((void**)&omega, g_omega);
    cudaGetSymbolAddress((void**)&segO, g_segO);
    cudaGetSymbolAddress((void**)&segE, g_segE);
    cudaGetSymbolAddress((void**)&cntH, g_cntH);
    cudaGetSymbolAddress((void**)&alpha, g_alpha);
    cudaGetSymbolAddress((void**)&eta, g_eta);
    cudaGetSymbolAddress((void**)&eemb, g_eemb);
    cudaGetSymbolAddress((void**)&eagg, g_eagg);
    cudaGetSymbolAddress((void**)&uagg, g_uagg);

    cudaMemsetAsync(mkey, 0, NU * sizeof(unsigned));
    cudaMemsetAsync(den, 0, NU * sizeof(float));
    cudaMemsetAsync(cntu, 0, NU * sizeof(float));
    cudaMemsetAsync(sv, 0, DD * sizeof(float));
    cudaMemsetAsync(segO, 0, NE * sizeof(float));
    cudaMemsetAsync(segE, 0, NE * sizeof(float));
    cudaMemsetAsync(cntH, 0, NE * sizeof(float));

    gemm64_kernel<<<(NU * 64 + 255) / 256, 256>>>(user_embed, Wq, Qu, NU);
    gemm64_kernel<<<(NI * 64 + 255) / 256, 256>>>(item_embed, Wk, Kt, NI);
    gemm64_kernel<<<(NI * 64 + 255) / 256, 256>>>(item_embed, Wv, Vt, NI);

    scores_kernel<<<(EIc + 7) / 8, 256>>>(Qu, Kt, inter_edge, inter_edge_w, scores, mkey);
    exp_kernel<<<(EIc + 255) / 256, 256>>>(inter_edge, scores, mkey, den, cntu);
    pref_kernel<<<512, 256>>>(Vt, inter_edge, scores, den, cntu, sv);

    const int SMEMB = 20932 * 4;
    cudaFuncSetAttribute(fact_router_kernel, cudaFuncAttributeMaxDynamicSharedMemorySize, SMEMB);
    fact_router_kernel<<<296, 256, SMEMB>>>(edge_index, edge_type, ent_real, ent_imag,
                                            rel_real, rel_imag, fp_W1, fp_b1, fp_W2, fp_b2,
                                            rt_W1, rt_b1, rt_W2, rt_b2, sv, omega);

    sego_kernel<<<(EK + 255) / 256, 256>>>(edge_index, omega, segO, cntH);
    alpha_kernel<<<(EK + 255) / 256, 256>>>(edge_index, omega, segO, alpha, eta, segE);
    eta_kernel<<<(EK + 255) / 256, 256>>>(edge_index, segE, eta);

    cudaMemcpyAsync(eemb, entity_emb, (size_t)NE * DD * sizeof(float), cudaMemcpyDeviceToDevice);
    cudaMemcpyAsync(out, entity_emb, (size_t)NE * DD * sizeof(float), cudaMemcpyDeviceToDevice);
    cudaMemcpyAsync(out + (size_t)NE * DD, user_emb, (size_t)NU * DD * sizeof(float),
                    cudaMemcpyDeviceToDevice);

    for (int hop = 1; hop <= 3; hop++) {
        cudaMemsetAsync(eagg, 0, (size_t)NE * DD * sizeof(float));
        cudaMemsetAsync(uagg, 0, (size_t)NU * DD * sizeof(float));
        const float* rho = (hop < 3) ? alpha : eta;
        kg_scatter_kernel<<<(EK + 15) / 16, 256>>>(edge_index, edge_type, relation_emb,
                                                   eemb, rho, eagg);
        ui_scatter_kernel<<<(EIc + 15) / 16, 256>>>(inter_edge, inter_edge_w, eemb, uagg);
        fin_ent_kernel<<<(NE + 7) / 8, 256>>>(eagg, cntH, eemb, out);
        fin_usr_kernel<<<(NU + 7) / 8, 256>>>(uagg, out + (size_t)NE * DD);
    }
}

// round 4
// speedup vs baseline: 1.7188x; 1.7188x over previous
#include <cuda_runtime.h>
#include <math.h>
#include <stdint.h>

#define NU 50000
#define NI 30000
#define NE 100000
#define EK 500000
#define EIc 1000000
#define DD 64
#define KD 32
#define NREL 10

// ---------------- scratch (module globals; no runtime allocation) ----------------
__device__ __align__(16) float g_Qu[NU * DD];
__device__ __align__(16) float g_Kt[NI * DD];
__device__ __align__(16) float g_Vt[NI * DD];
__device__ __align__(16) float g_scores[EIc];
// combined small scratch, zeroed with ONE memset:
// [0,NU): mkey  [NU,2NU): den  [2NU,3NU): cntu  [3NU,3NU+64): sv
// [3NU+64, 3NU+129): c (64 + const)   [3NU+129, +NE): segO  [+NE): segE  [+NE): cntH
#define OFF_MKEY 0
#define OFF_DEN   (NU)
#define OFF_CNTU  (2 * NU)
#define OFF_SV    (3 * NU)
#define OFF_C     (3 * NU + 64)
#define OFF_SEGO  (3 * NU + 129)
#define OFF_SEGE  (OFF_SEGO + NE)
#define OFF_CNTH  (OFF_SEGE + NE)
#define SMALL_TOT (OFF_CNTH + NE)
__device__ __align__(16) float g_small[SMALL_TOT];
__device__ __align__(16) float g_omega[EK];
__device__ __align__(16) float g_alpha[EK];
__device__ __align__(16) float g_eta[EK];
__device__ __align__(16) float g_P[NE * 192];     // per-entity [A1(64) | A3(64) | B1(64)]
__device__ __align__(16) float g_relA[NREL * 64]; // A2
__device__ __align__(16) float g_relB[NREL * 64]; // B2
__device__ __align__(16) float g_eemb[NE * DD];
__device__ __align__(16) float g_eagg[NE * DD];
__device__ __align__(16) float g_uagg[NU * DD];

// ---------------- helpers ----------------
__device__ __forceinline__ unsigned fkey(float f) {
    unsigned b = __float_as_uint(f);
    return (b & 0x80000000u) ? ~b : (b | 0x80000000u);
}
__device__ __forceinline__ float fdecode(unsigned k) {
    unsigned b = (k & 0x80000000u) ? (k ^ 0x80000000u) : ~k;
    return __uint_as_float(b);
}
__device__ __forceinline__ float n2n(float x) {
    if (isnan(x)) return 0.f;
    if (isinf(x)) return (x > 0.f) ? 1e4f : 1e-4f;
    return x;
}
__device__ __forceinline__ void redAdd4(float* p, float4 v) {
    asm volatile("red.global.add.v4.f32 [%0], {%1, %2, %3, %4};"
                 :: "l"(p), "f"(v.x), "f"(v.y), "f"(v.z), "f"(v.w)
                 : "memory");
}
__device__ __forceinline__ float fsig(float x) { return 1.f / (1.f + __expf(-x)); }

// ---------------- kernels ----------------

// O[rows,64] = A[rows,64] @ W[64,64]
__global__ void gemm64_kernel(const float* __restrict__ A, const float* __restrict__ W,
                              float* __restrict__ O, int rows) {
    __shared__ float sW[4096];
    for (int i = threadIdx.x; i < 4096; i += blockDim.x) sW[i] = W[i];
    __syncthreads();
    int idx = blockIdx.x * blockDim.x + threadIdx.x;
    if (idx >= rows * 64) return;
    int r = idx >> 6, c = idx & 63;
    const float* a = A + (r << 6);
    float acc = 0.f;
#pragma unroll
    for (int k = 0; k < 64; k++) acc = fmaf(a[k], sW[(k << 6) + c], acc);
    O[idx] = acc;
}

// P[n] = [A1 | A3 | B1], each = [entR[n]|entI[n]] @ (64x64 block)
__global__ __launch_bounds__(256) void precompP_kernel(
    const float* __restrict__ entR, const float* __restrict__ entI,
    const float* __restrict__ fpW1, const float* __restrict__ rtW1,
    float* __restrict__ P) {
    __shared__ float sW[64 * 192];  // sW[k*192 + j]
    for (int i = threadIdx.x; i < 64 * 192; i += blockDim.x) {
        int k = i / 192, j = i % 192;
        float v;
        if (j < 64) v = fpW1[k * 64 + j];
        else if (j < 128) v = fpW1[(128 + k) * 64 + (j - 64)];
        else v = rtW1[k * 64 + (j - 128)];
        sW[i] = v;
    }
    __syncthreads();
    int lane = threadIdx.x & 31;
    int nw = gridDim.x * (blockDim.x >> 5);
    const float2* sWv = (const float2*)sW;
    for (int n = blockIdx.x * (blockDim.x >> 5) + (threadIdx.x >> 5); n < NE; n += nw) {
        float x0 = entR[n * 32 + lane];
        float x1 = entI[n * 32 + lane];
        float2 a0 = make_float2(0.f, 0.f), a1 = make_float2(0.f, 0.f), a2 = make_float2(0.f, 0.f);
#pragma unroll
        for (int l0 = 0; l0 < 32; l0++) {
            float f = __shfl_sync(0xffffffffu, x0, l0);
            const float2* row = sWv + l0 * 96;
            float2 w0 = row[lane], w1 = row[lane + 32], w2 = row[lane + 64];
            a0.x = fmaf(f, w0.x, a0.x); a0.y = fmaf(f, w0.y, a0.y);
            a1.x = fmaf(f, w1.x, a1.x); a1.y = fmaf(f, w1.y, a1.y);
            a2.x = fmaf(f, w2.x, a2.x); a2.y = fmaf(f, w2.y, a2.y);
        }
#pragma unroll
        for (int l0 = 0; l0 < 32; l0++) {
            float f = __shfl_sync(0xffffffffu, x1, l0);
            const float2* row = sWv + (32 + l0) * 96;
            float2 w0 = row[lane], w1 = row[lane + 32], w2 = row[lane + 64];
            a0.x = fmaf(f, w0.x, a0.x); a0.y = fmaf(f, w0.y, a0.y);
            a1.x = fmaf(f, w1.x, a1.x); a1.y = fmaf(f, w1.y, a1.y);
            a2.x = fmaf(f, w2.x, a2.x); a2.y = fmaf(f, w2.y, a2.y);
        }
        float2* Pr = (float2*)(P + n * 192);
        Pr[lane] = a0; Pr[lane + 32] = a1; Pr[lane + 64] = a2;
    }
}

// relation precompute: A2[r] = [rr|ri]@fpW1[64:128], B2[r] = [rr|ri]@rtW1
__global__ void relAB_kernel(const float* __restrict__ relR, const float* __restrict__ relI,
                             const float* __restrict__ fpW1, const float* __restrict__ rtW1,
                             float* __restrict__ relA, float* __restrict__ relB) {
    int t = blockIdx.x * blockDim.x + threadIdx.x;
    if (t >= NREL * 64) return;
    int r = t >> 6, j = t & 63;
    float a = 0.f, b = 0.f;
#pragma unroll
    for (int k = 0; k < 32; k++) {
        float xr = relR[r * 32 + k], xi = relI[r * 32 + k];
        a = fmaf(xr, fpW1[(64 + k) * 64 + j], a);
        a = fmaf(xi, fpW1[(96 + k) * 64 + j], a);
        b = fmaf(xr, rtW1[k * 64 + j], b);
        b = fmaf(xi, rtW1[(32 + k) * 64 + j], b);
    }
    relA[t] = a; relB[t] = b;
}

// warp per interaction edge: score = dot(q,k)/8 * w;  segment max via atomicMax
__global__ void scores_kernel(const float* __restrict__ Qu, const float* __restrict__ Kt,
                              const int* __restrict__ inter, const float* __restrict__ iw,
                              float* __restrict__ scores, unsigned* __restrict__ mkey) {
    int e = blockIdx.x * (blockDim.x >> 5) + (threadIdx.x >> 5);
    if (e >= EIc) return;
    int lane = threadIdx.x & 31;
    int u = inter[e], it = inter[EIc + e];
    const float* q = Qu + u * 64;
    const float* k = Kt + it * 64;
    float p = q[lane] * k[lane] + q[lane + 32] * k[lane + 32];
#pragma unroll
    for (int o = 16; o; o >>= 1) p += __shfl_xor_sync(0xffffffffu, p, o);
    if (lane == 0) {
        float sc = p * 0.125f * iw[e];
        scores[e] = sc;
        atomicMax(&mkey[u], fkey(sc));
    }
}

__global__ void exp_kernel(const int* __restrict__ inter, float* __restrict__ scores,
                           const unsigned* __restrict__ mkey, float* __restrict__ den,
                           float* __restrict__ cntu) {
    int e = blockIdx.x * blockDim.x + threadIdx.x;
    if (e >= EIc) return;
    int u = inter[e];
    float m = fdecode(mkey[u]);
    float ex = __expf(scores[e] - m);
    scores[e] = ex;
    atomicAdd(&den[u], ex);
    atomicAdd(&cntu[u], 1.f);
}

// s[d] = sum_e (alpha_e / max(cnt_u,1)) * V[item_e][d]
__global__ void pref_kernel(const float* __restrict__ Vt, const int* __restrict__ inter,
                            const float* __restrict__ exv, const float* __restrict__ den,
                            const float* __restrict__ cntu, float* __restrict__ s) {
    __shared__ float sacc[64];
    if (threadIdx.x < 64) sacc[threadIdx.x] = 0.f;
    __syncthreads();
    int lane = threadIdx.x & 31;
    int nw = gridDim.x * (blockDim.x >> 5);
    float a0 = 0.f, a1 = 0.f;
    for (int e = blockIdx.x * (blockDim.x >> 5) + (threadIdx.x >> 5); e < EIc; e += nw) {
        int u = inter[e], it = inter[EIc + e];
        float coef = exv[e] / den[u] / fmaxf(cntu[u], 1.f);
        const float* v = Vt + it * 64;
        a0 = fmaf(coef, v[lane], a0);
        a1 = fmaf(coef, v[lane + 32], a1);
    }
    atomicAdd(&sacc[lane], a0);
    atomicAdd(&sacc[lane + 32], a1);
    __syncthreads();
    if (threadIdx.x < 64) atomicAdd(&s[threadIdx.x], sacc[threadIdx.x]);
}

// c[i] = rtW2[i,:] . s ;  c[64] = rtb2 . s
__global__ void cvec_kernel(const float* __restrict__ rtW2, const float* __restrict__ rtb2,
                            const float* __restrict__ sv, float* __restrict__ c) {
    __shared__ float ss[64];
    int i = threadIdx.x;
    if (i < 64) ss[i] = sv[i];
    __syncthreads();
    if (i < 64) {
        float acc = 0.f;
#pragma unroll
        for (int j = 0; j < 64; j++) acc = fmaf(rtW2[i * 64 + j], ss[j], acc);
        c[i] = acc;
        if (i == 0) {
            float d = 0.f;
            for (int j = 0; j < 64; j++) d = fmaf(rtb2[j], ss[j], d);
            c[64] = d;
        }
    }
}

// warp per KG edge, factorized fact-semantic + router -> omega
__global__ __launch_bounds__(256) void fact2_kernel(
    const int* __restrict__ eidx, const int* __restrict__ etype,
    const float* __restrict__ P, const float* __restrict__ relA,
    const float* __restrict__ relB, const float* __restrict__ fpb1,
    const float* __restrict__ fpW2, const float* __restrict__ fpb2,
    const float* __restrict__ rtb1, const float* __restrict__ cvec,
    float* __restrict__ omega) {
    __shared__ float sA2[NREL * 64], sB2[NREL * 64];
    __shared__ float sb1[64], srb1[64], sc[64], sW2[192];
    __shared__ float sb2[3], sdc;
    for (int i = threadIdx.x; i < NREL * 64; i += blockDim.x) { sA2[i] = relA[i]; sB2[i] = relB[i]; }
    if (threadIdx.x < 64) {
        sb1[threadIdx.x] = fpb1[threadIdx.x];
        srb1[threadIdx.x] = rtb1[threadIdx.x];
        sc[threadIdx.x] = cvec[threadIdx.x];
    }
    if (threadIdx.x < 192) sW2[threadIdx.x] = fpW2[threadIdx.x];
    if (threadIdx.x < 3) sb2[threadIdx.x] = fpb2[threadIdx.x];
    if (threadIdx.x == 0) sdc = cvec[64];
    __syncthreads();

    int lane = threadIdx.x & 31;
    int nw = gridDim.x * (blockDim.x >> 5);
    for (int e = blockIdx.x * (blockDim.x >> 5) + (threadIdx.x >> 5); e < EK; e += nw) {
        int hh = eidx[e], tt = eidx[EK + e], rr = etype[e] - 1;
        const float2* Ph = (const float2*)(P + hh * 192);
        const float2* Pt = (const float2*)(P + tt * 192);
        float2 a1 = Ph[lane];
        float2 a3 = Pt[lane + 32];
        float2 b1h = Ph[lane + 64];
        float2 b1t = Pt[lane + 64];
        float2 a2 = *(const float2*)(sA2 + rr * 64 + 2 * lane);
        float hx = fsig(a1.x + a3.x + a2.x + sb1[2 * lane]);
        float hy = fsig(a1.y + a3.y + a2.y + sb1[2 * lane + 1]);
        float p0 = hx * sW2[(2 * lane) * 3 + 0] + hy * sW2[(2 * lane + 1) * 3 + 0];
        float p1 = hx * sW2[(2 * lane) * 3 + 1] + hy * sW2[(2 * lane + 1) * 3 + 1];
        float p2 = hx * sW2[(2 * lane) * 3 + 2] + hy * sW2[(2 * lane + 1) * 3 + 2];
#pragma unroll
        for (int o = 16; o; o >>= 1) {
            p0 += __shfl_xor_sync(0xffffffffu, p0, o);
            p1 += __shfl_xor_sync(0xffffffffu, p1, o);
            p2 += __shfl_xor_sync(0xffffffffu, p2, o);
        }
        p0 += sb2[0]; p1 += sb2[1]; p2 += sb2[2];
        float mx = fmaxf(p0, fmaxf(p1, p2));
        float e0 = __expf(p0 - mx), e1 = __expf(p1 - mx), e2 = __expf(p2 - mx);
        float inv = 1.f / (e0 + e1 + e2);
        float w0 = e0 * inv, w1 = e1 * inv, w2 = e2 * inv;
        float2 b2r = *(const float2*)(sB2 + rr * 64 + 2 * lane);
        float gx = fsig(w0 * b1h.x + w1 * b2r.x + w2 * b1t.x + srb1[2 * lane]);
        float gy = fsig(w0 * b1h.y + w1 * b2r.y + w2 * b1t.y + srb1[2 * lane + 1]);
        float pp = gx * sc[2 * lane] + gy * sc[2 * lane + 1];
#pragma unroll
        for (int o = 16; o; o >>= 1) pp += __shfl_xor_sync(0xffffffffu, pp, o);
        if (lane == 0) omega[e] = (pp + sdc) * 0.125f;
    }
}

__global__ void sego_kernel(const int* __restrict__ eidx, const float* __restrict__ omega,
                            float* __restrict__ segO, float* __restrict__ cntH) {
    int e = blockIdx.x * blockDim.x + threadIdx.x;
    if (e >= EK) return;
    int hh = eidx[e];
    atomicAdd(&segO[hh], omega[e]);
    atomicAdd(&cntH[hh], 1.f);
}

__global__ void alpha_kernel(const int* __restrict__ eidx, const float* __restrict__ omega,
                             const float* __restrict__ segO, float* __restrict__ alpha,
                             float* __restrict__ eta, float* __restrict__ segE) {
    int e = blockIdx.x * blockDim.x + threadIdx.x;
    if (e >= EK) return;
    int hh = eidx[e];
    float a = omega[e] / (segO[hh] + 1e-8f);
    alpha[e] = a;
    float et = (a > 0.2f) ? a : 0.f;
    eta[e] = et;
    if (et != 0.f) atomicAdd(&segE[hh], et);
}

__global__ void eta_kernel(const int* __restrict__ eidx, const float* __restrict__ segE,
                           float* __restrict__ eta) {
    int e = blockIdx.x * blockDim.x + threadIdx.x;
    if (e >= EK) return;
    int hh = eidx[e];
    eta[e] = eta[e] / (segE[hh] + 1e-8f);
}

// fused kg + ui scatter (16 lanes/edge, red.v4)
#define KGB ((EK + 15) / 16)
#define UIB ((EIc + 15) / 16)
__global__ void scatter_all_kernel(const int* __restrict__ eidx, const int* __restrict__ etype,
                                   const float* __restrict__ relemb, const float* __restrict__ eemb,
                                   const float* __restrict__ rho, float* __restrict__ eagg,
                                   const int* __restrict__ inter, const float* __restrict__ iw,
                                   float* __restrict__ uagg) {
    int b = blockIdx.x;
    int sub = threadIdx.x >> 4;
    int d0 = (threadIdx.x & 15) << 2;
    if (b < KGB) {
        int e = b * 16 + sub;
        if (e >= EK) return;
        int hh = eidx[e], tt = eidx[EK + e], rr = etype[e] - 1;
        float rh = rho[e];
        float4 ev = *(const float4*)(eemb + tt * 64 + d0);
        float4 rv = *(const float4*)(relemb + rr * 64 + d0);
        redAdd4(eagg + hh * 64 + d0,
                make_float4(ev.x * rv.x * rh, ev.y * rv.y * rh, ev.z * rv.z * rh, ev.w * rv.w * rh));
    } else {
        int e = (b - KGB) * 16 + sub;
        if (e >= EIc) return;
        int u = inter[e], it = inter[EIc + e];
        float w = iw[e];
        float4 ev = *(const float4*)(eemb + it * 64 + d0);
        redAdd4(uagg + u * 64 + d0, make_float4(ev.x * w, ev.y * w, ev.z * w, ev.w * w));
    }
}

// fused finalize: normalize, accumulate into out, write eemb, zero agg for next hop
#define ENB ((NE + 7) / 8)
#define UNB ((NU + 7) / 8)
__global__ void fin_all_kernel(float* __restrict__ eagg, const float* __restrict__ cntH,
                               float* __restrict__ eemb, float* __restrict__ uagg,
                               float* __restrict__ oute, float* __restrict__ outu) {
    int b = blockIdx.x;
    int lane = threadIdx.x & 31;
    if (b < ENB) {
        int n = b * 8 + (threadIdx.x >> 5);
        if (n >= NE) return;
        float inv = 1.f / fmaxf(cntH[n], 1.f);
        float2* pe = (float2*)(eagg + n * 64 + 2 * lane);
        float2 v = *pe;
        *pe = make_float2(0.f, 0.f);
        v.x *= inv; v.y *= inv;
        float ss = v.x * v.x + v.y * v.y;
#pragma unroll
        for (int o = 16; o; o >>= 1) ss += __shfl_xor_sync(0xffffffffu, ss, o);
        float invn = 1.f / fmaxf(sqrtf(ss), 1e-8f);
        float a = n2n(v.x * invn), bb = n2n(v.y * invn);
        *(float2*)(eemb + n * 64 + 2 * lane) = make_float2(a, bb);
        float2 o2 = *(float2*)(oute + n * 64 + 2 * lane);
        o2.x += a; o2.y += bb;
        *(float2*)(oute + n * 64 + 2 * lane) = o2;
    } else {
        int n = (b - ENB) * 8 + (threadIdx.x >> 5);
        if (n >= NU) return;
        float2* pu = (float2*)(uagg + n * 64 + 2 * lane);
        float2 v = *pu;
        *pu = make_float2(0.f, 0.f);
        float ss = v.x * v.x + v.y * v.y;
#pragma unroll
        for (int o = 16; o; o >>= 1) ss += __shfl_xor_sync(0xffffffffu, ss, o);
        float invn = 1.f / fmaxf(sqrtf(ss), 1e-8f);
        float a = n2n(v.x * invn), bb = n2n(v.y * invn);
        float2 o2 = *(float2*)(outu + n * 64 + 2 * lane);
        o2.x += a; o2.y += bb;
        *(float2*)(outu + n * 64 + 2 * lane) = o2;
    }
}

// ---------------- host launch ----------------
extern "C" void kernel_launch(void* const* d_in, const int* in_sizes, int n_in,
                              void* d_out, int out_size) {
    const float* user_embed = (const float*)d_in[0];
    const float* item_embed = (const float*)d_in[1];
    const float* Wq = (const float*)d_in[2];
    const float* Wk = (const float*)d_in[3];
    const float* Wv = (const float*)d_in[4];
    const float* ent_real = (const float*)d_in[5];
    const float* ent_imag = (const float*)d_in[6];
    const float* rel_real = (const float*)d_in[7];
    const float* rel_imag = (const float*)d_in[8];
    const float* fp_W1 = (const float*)d_in[9];
    const float* fp_b1 = (const float*)d_in[10];
    const float* fp_W2 = (const float*)d_in[11];
    const float* fp_b2 = (const float*)d_in[12];
    const float* rt_W1 = (const float*)d_in[13];
    const float* rt_b1 = (const float*)d_in[14];
    const float* rt_W2 = (const float*)d_in[15];
    const float* rt_b2 = (const float*)d_in[16];
    const float* relation_emb = (const float*)d_in[17];
    const float* user_emb = (const float*)d_in[18];
    const float* entity_emb = (const float*)d_in[19];
    const float* inter_edge_w = (const float*)d_in[20];
    const int* edge_index = (const int*)d_in[21];
    const int* edge_type = (const int*)d_in[22];
    const int* inter_edge = (const int*)d_in[23];
    float* out = (float*)d_out;

    float *Qu, *Kt, *Vt, *scores, *small, *omega, *alpha, *eta, *P, *relA, *relB;
    float *eemb, *eagg, *uagg;
    cudaGetSymbolAddress((void**)&Qu, g_Qu);
    cudaGetSymbolAddress((void**)&Kt, g_Kt);
    cudaGetSymbolAddress((void**)&Vt, g_Vt);
    cudaGetSymbolAddress((void**)&scores, g_scores);
    cudaGetSymbolAddress((void**)&small, g_small);
    cudaGetSymbolAddress((void**)&omega, g_omega);
    cudaGetSymbolAddress((void**)&alpha, g_alpha);
    cudaGetSymbolAddress((void**)&eta, g_eta);
    cudaGetSymbolAddress((void**)&P, g_P);
    cudaGetSymbolAddress((void**)&relA, g_relA);
    cudaGetSymbolAddress((void**)&relB, g_relB);
    cudaGetSymbolAddress((void**)&eemb, g_eemb);
    cudaGetSymbolAddress((void**)&eagg, g_eagg);
    cudaGetSymbolAddress((void**)&uagg, g_uagg);

    unsigned* mkey = (unsigned*)(small + OFF_MKEY);
    float* den = small + OFF_DEN;
    float* cntu = small + OFF_CNTU;
    float* sv = small + OFF_SV;
    float* cvec = small + OFF_C;
    float* segO = small + OFF_SEGO;
    float* segE = small + OFF_SEGE;
    float* cntH = small + OFF_CNTH;

    cudaMemsetAsync(small, 0, SMALL_TOT * sizeof(float));

    // independent precomputes
    precompP_kernel<<<1184, 256>>>(ent_real, ent_imag, fp_W1, rt_W1, P);
    relAB_kernel<<<(NREL * 64 + 255) / 256, 256>>>(rel_real, rel_imag, fp_W1, rt_W1, relA, relB);

    gemm64_kernel<<<(NU * 64 + 255) / 256, 256>>>(user_embed, Wq, Qu, NU);
    gemm64_kernel<<<(NI * 64 + 255) / 256, 256>>>(item_embed, Wk, Kt, NI);
    gemm64_kernel<<<(NI * 64 + 255) / 256, 256>>>(item_embed, Wv, Vt, NI);

    scores_kernel<<<(EIc + 7) / 8, 256>>>(Qu, Kt, inter_edge, inter_edge_w, scores, mkey);
    exp_kernel<<<(EIc + 255) / 256, 256>>>(inter_edge, scores, mkey, den, cntu);
    pref_kernel<<<512, 256>>>(Vt, inter_edge, scores, den, cntu, sv);
    cvec_kernel<<<1, 64>>>(rt_W2, rt_b2, sv, cvec);

    fact2_kernel<<<1184, 256>>>(edge_index, edge_type, P, relA, relB, fp_b1, fp_W2, fp_b2,
                                rt_b1, cvec, omega);

    sego_kernel<<<(EK + 255) / 256, 256>>>(edge_index, omega, segO, cntH);
    alpha_kernel<<<(EK + 255) / 256, 256>>>(edge_index, omega, segO, alpha, eta, segE);
    eta_kernel<<<(EK + 255) / 256, 256>>>(edge_index, segE, eta);

    cudaMemcpyAsync(eemb, entity_emb, (size_t)NE * DD * sizeof(float), cudaMemcpyDeviceToDevice);
    cudaMemcpyAsync(out, entity_emb, (size_t)NE * DD * sizeof(float), cudaMemcpyDeviceToDevice);
    cudaMemcpyAsync(out + (size_t)NE * DD, user_emb, (size_t)NU * DD * sizeof(float),
                    cudaMemcpyDeviceToDevice);

    for (int hop = 1; hop <= 3; hop++) {
        const float* rho = (hop < 3) ? alpha : eta;
        scatter_all_kernel<<<KGB + UIB, 256>>>(edge_index, edge_type, relation_emb, eemb, rho,
                                               eagg, inter_edge, inter_edge_w, uagg);
        fin_all_kernel<<<ENB + UNB, 256>>>(eagg, cntH, eemb, uagg, out, out + (size_t)NE * DD);
    }
}

// round 5
// speedup vs baseline: 2.5955x; 1.5101x over previous
#include <cuda_runtime.h>
#include <math.h>
#include <stdint.h>

#define NU 50000
#define NI 30000
#define NE 100000
#define EK 500000
#define EIc 1000000
#define DD 64
#define KD 32
#define NREL 10

// ---------------- scratch (module globals; no runtime allocation) ----------------
__device__ __align__(16) float g_Qu[NU * DD];
__device__ __align__(16) float g_Kt[NI * DD];
__device__ __align__(16) float g_Vt[NI * DD];
__device__ __align__(16) float g_scores[EIc];
// zeroed float scratch: [0,NU): mkey  [NU,2NU): den  [2NU,2NU+64): sv  [2NU+64, 2NU+129): cvec
#define OFF_MKEY 0
#define OFF_DEN  (NU)
#define OFF_SV   (2 * NU)
#define OFF_C    (2 * NU + 64)
#define SMALLF_TOT (2 * NU + 129)
__device__ __align__(16) float g_smallf[SMALLF_TOT];
// zeroed int scratch: cntHi[NE], curH[NE], cntUi[NU], curU[NU]
#define IOFF_CNTH 0
#define IOFF_CURH (NE)
#define IOFF_CNTU (2 * NE)
#define IOFF_CURU (2 * NE + NU)
#define SMALLI_TOT (2 * NE + 2 * NU)
__device__ __align__(16) int g_smalli[SMALLI_TOT];
__device__ __align__(16) int g_offH[NE];
__device__ __align__(16) int g_offU[NU];
__device__ __align__(16) int g_bsumH[128];
__device__ __align__(16) int g_bsumU[128];
__device__ __align__(16) int g_kg_tr[EK];
__device__ __align__(16) int g_kg_eid[EK];
__device__ __align__(16) int g_ui_item[EIc];
__device__ __align__(16) float g_ui_w[EIc];
__device__ __align__(16) float g_rho_a[EK];
__device__ __align__(16) float g_rho_e[EK];
__device__ __align__(16) float g_omega[EK];
__device__ __align__(16) float g_P[NE * 192];     // per-entity [A1(64) | A3(64) | B1(64)]
__device__ __align__(16) float g_relA[NREL * 64]; // A2
__device__ __align__(16) float g_relB[NREL * 64]; // B2
__device__ __align__(16) float g_eembA[NE * DD];
__device__ __align__(16) float g_eembB[NE * DD];

// ---------------- helpers ----------------
__device__ __forceinline__ unsigned fkey(float f) {
    unsigned b = __float_as_uint(f);
    return (b & 0x80000000u) ? ~b : (b | 0x80000000u);
}
__device__ __forceinline__ float fdecode(unsigned k) {
    unsigned b = (k & 0x80000000u) ? (k ^ 0x80000000u) : ~k;
    return __uint_as_float(b);
}
__device__ __forceinline__ float n2n(float x) {
    if (isnan(x)) return 0.f;
    if (isinf(x)) return (x > 0.f) ? 1e4f : 1e-4f;
    return x;
}
__device__ __forceinline__ float fsig(float x) { return 1.f / (1.f + __expf(-x)); }

// ---------------- CSR build ----------------
__global__ void count_kernel(const int* __restrict__ eidx, const int* __restrict__ inter,
                             int* __restrict__ cntHi, int* __restrict__ cntUi) {
    int i = blockIdx.x * blockDim.x + threadIdx.x;
    if (i < EK) atomicAdd(&cntHi[eidx[i]], 1);
    if (i < EIc) atomicAdd(&cntUi[inter[i]], 1);
}

__global__ void scan1_kernel(const int* __restrict__ cnt, int n, int* __restrict__ excl,
                             int* __restrict__ bsum) {
    __shared__ int sh[1024];
    int tid = threadIdx.x;
    int i = blockIdx.x * 1024 + tid;
    int v = (i < n) ? cnt[i] : 0;
    sh[tid] = v; __syncthreads();
    for (int st = 1; st < 1024; st <<= 1) {
        int t = (tid >= st) ? sh[tid - st] : 0; __syncthreads();
        sh[tid] += t; __syncthreads();
    }
    if (i < n) excl[i] = sh[tid] - v;
    if (tid == 1023) bsum[blockIdx.x] = sh[1023];
}
__global__ void scan2_kernel(int* __restrict__ bsum, int nb) {
    __shared__ int sh[1024];
    int tid = threadIdx.x;
    int v = (tid < nb) ? bsum[tid] : 0;
    sh[tid] = v; __syncthreads();
    for (int st = 1; st < 1024; st <<= 1) {
        int t = (tid >= st) ? sh[tid - st] : 0; __syncthreads();
        sh[tid] += t; __syncthreads();
    }
    if (tid < nb) bsum[tid] = sh[tid] - v;
}
__global__ void scan3_kernel(int* __restrict__ excl, const int* __restrict__ bsum, int n) {
    int i = blockIdx.x * 1024 + threadIdx.x;
    if (i < n) excl[i] += bsum[blockIdx.x];
}

__global__ void fillKG_kernel(const int* __restrict__ eidx, const int* __restrict__ etype,
                              const int* __restrict__ offH, int* __restrict__ curH,
                              int* __restrict__ kg_tr, int* __restrict__ kg_eid) {
    int e = blockIdx.x * blockDim.x + threadIdx.x;
    if (e >= EK) return;
    int h = eidx[e];
    int pos = offH[h] + atomicAdd(&curH[h], 1);
    kg_tr[pos] = (eidx[EK + e] << 4) | (etype[e] - 1);
    kg_eid[pos] = e;
}
__global__ void fillUI_kernel(const int* __restrict__ inter, const float* __restrict__ iw,
                              const int* __restrict__ offU, int* __restrict__ curU,
                              int* __restrict__ ui_item, float* __restrict__ ui_w) {
    int e = blockIdx.x * blockDim.x + threadIdx.x;
    if (e >= EIc) return;
    int u = inter[e];
    int pos = offU[u] + atomicAdd(&curU[u], 1);
    ui_item[pos] = inter[EIc + e];
    ui_w[pos] = iw[e];
}

// ---------------- small GEMM / precompute ----------------
// O[rows,64] = A[rows,64] @ W[64,64], 4 outputs/thread
__global__ void gemm64_kernel(const float* __restrict__ A, const float* __restrict__ W,
                              float* __restrict__ O, int rows) {
    __shared__ float sW[4096];
    for (int i = threadIdx.x; i < 4096; i += blockDim.x) sW[i] = W[i];
    __syncthreads();
    int t = blockIdx.x * blockDim.x + threadIdx.x;
    if (t >= rows * 16) return;
    int r = t >> 4, c4 = (t & 15) << 2;
    const float4* a4 = (const float4*)(A + (r << 6));
    float4 acc = make_float4(0.f, 0.f, 0.f, 0.f);
#pragma unroll
    for (int k4 = 0; k4 < 16; k4++) {
        float4 av = a4[k4];
        float4 w0 = *(const float4*)&sW[(k4 * 4 + 0) * 64 + c4];
        float4 w1 = *(const float4*)&sW[(k4 * 4 + 1) * 64 + c4];
        float4 w2 = *(const float4*)&sW[(k4 * 4 + 2) * 64 + c4];
        float4 w3 = *(const float4*)&sW[(k4 * 4 + 3) * 64 + c4];
        acc.x = fmaf(av.x, w0.x, fmaf(av.y, w1.x, fmaf(av.z, w2.x, fmaf(av.w, w3.x, acc.x))));
        acc.y = fmaf(av.x, w0.y, fmaf(av.y, w1.y, fmaf(av.z, w2.y, fmaf(av.w, w3.y, acc.y))));
        acc.z = fmaf(av.x, w0.z, fmaf(av.y, w1.z, fmaf(av.z, w2.z, fmaf(av.w, w3.z, acc.z))));
        acc.w = fmaf(av.x, w0.w, fmaf(av.y, w1.w, fmaf(av.z, w2.w, fmaf(av.w, w3.w, acc.w))));
    }
    *(float4*)&O[(r << 6) + c4] = acc;
}

// P[n] = [A1 | A3 | B1]
__global__ __launch_bounds__(256) void precompP_kernel(
    const float* __restrict__ entR, const float* __restrict__ entI,
    const float* __restrict__ fpW1, const float* __restrict__ rtW1,
    float* __restrict__ P) {
    __shared__ float sW[64 * 192];
    for (int i = threadIdx.x; i < 64 * 192; i += blockDim.x) {
        int k = i / 192, j = i % 192;
        float v;
        if (j < 64) v = fpW1[k * 64 + j];
        else if (j < 128) v = fpW1[(128 + k) * 64 + (j - 64)];
        else v = rtW1[k * 64 + (j - 128)];
        sW[i] = v;
    }
    __syncthreads();
    int lane = threadIdx.x & 31;
    int nw = gridDim.x * (blockDim.x >> 5);
    const float2* sWv = (const float2*)sW;
    for (int n = blockIdx.x * (blockDim.x >> 5) + (threadIdx.x >> 5); n < NE; n += nw) {
        float x0 = entR[n * 32 + lane];
        float x1 = entI[n * 32 + lane];
        float2 a0 = make_float2(0.f, 0.f), a1 = make_float2(0.f, 0.f), a2 = make_float2(0.f, 0.f);
#pragma unroll
        for (int l0 = 0; l0 < 32; l0++) {
            float f = __shfl_sync(0xffffffffu, x0, l0);
            const float2* row = sWv + l0 * 96;
            float2 w0 = row[lane], w1 = row[lane + 32], w2 = row[lane + 64];
            a0.x = fmaf(f, w0.x, a0.x); a0.y = fmaf(f, w0.y, a0.y);
            a1.x = fmaf(f, w1.x, a1.x); a1.y = fmaf(f, w1.y, a1.y);
            a2.x = fmaf(f, w2.x, a2.x); a2.y = fmaf(f, w2.y, a2.y);
        }
#pragma unroll
        for (int l0 = 0; l0 < 32; l0++) {
            float f = __shfl_sync(0xffffffffu, x1, l0);
            const float2* row = sWv + (32 + l0) * 96;
            float2 w0 = row[lane], w1 = row[lane + 32], w2 = row[lane + 64];
            a0.x = fmaf(f, w0.x, a0.x); a0.y = fmaf(f, w0.y, a0.y);
            a1.x = fmaf(f, w1.x, a1.x); a1.y = fmaf(f, w1.y, a1.y);
            a2.x = fmaf(f, w2.x, a2.x); a2.y = fmaf(f, w2.y, a2.y);
        }
        float2* Pr = (float2*)(P + n * 192);
        Pr[lane] = a0; Pr[lane + 32] = a1; Pr[lane + 64] = a2;
    }
}

__global__ void relAB_kernel(const float* __restrict__ relR, const float* __restrict__ relI,
                             const float* __restrict__ fpW1, const float* __restrict__ rtW1,
                             float* __restrict__ relA, float* __restrict__ relB) {
    int t = blockIdx.x * blockDim.x + threadIdx.x;
    if (t >= NREL * 64) return;
    int r = t >> 6, j = t & 63;
    float a = 0.f, b = 0.f;
#pragma unroll
    for (int k = 0; k < 32; k++) {
        float xr = relR[r * 32 + k], xi = relI[r * 32 + k];
        a = fmaf(xr, fpW1[(64 + k) * 64 + j], a);
        a = fmaf(xi, fpW1[(96 + k) * 64 + j], a);
        b = fmaf(xr, rtW1[k * 64 + j], b);
        b = fmaf(xi, rtW1[(32 + k) * 64 + j], b);
    }
    relA[t] = a; relB[t] = b;
}

// ---------------- attention preference ----------------
// 16 lanes per edge (2 edges/warp), float4 loads
__global__ void scores_kernel(const float* __restrict__ Qu, const float* __restrict__ Kt,
                              const int* __restrict__ inter, const float* __restrict__ iw,
                              float* __restrict__ scores, unsigned* __restrict__ mkey) {
    int gw = blockIdx.x * (blockDim.x >> 5) + (threadIdx.x >> 5);
    int lane = threadIdx.x & 31;
    int e = gw * 2 + (lane >> 4);
    if (e >= EIc) return;
    int sl = lane & 15;
    int u = inter[e], it = inter[EIc + e];
    float4 q = *(const float4*)(Qu + u * 64 + sl * 4);
    float4 k = *(const float4*)(Kt + it * 64 + sl * 4);
    float p = q.x * k.x + q.y * k.y + q.z * k.z + q.w * k.w;
#pragma unroll
    for (int o = 8; o; o >>= 1) p += __shfl_xor_sync(0xffffffffu, p, o);
    if (sl == 0) {
        float sc = p * 0.125f * iw[e];
        scores[e] = sc;
        atomicMax(&mkey[u], fkey(sc));
    }
}

__global__ void exp_kernel(const int* __restrict__ inter, float* __restrict__ scores,
                           const unsigned* __restrict__ mkey, float* __restrict__ den) {
    int e = blockIdx.x * blockDim.x + threadIdx.x;
    if (e >= EIc) return;
    int u = inter[e];
    float m = fdecode(mkey[u]);
    float ex = __expf(scores[e] - m);
    scores[e] = ex;
    atomicAdd(&den[u], ex);
}

__global__ void pref_kernel(const float* __restrict__ Vt, const int* __restrict__ inter,
                            const float* __restrict__ exv, const float* __restrict__ den,
                            const int* __restrict__ cntUi, float* __restrict__ s) {
    __shared__ float sacc[64];
    if (threadIdx.x < 64) sacc[threadIdx.x] = 0.f;
    __syncthreads();
    int lane = threadIdx.x & 31;
    int nw = gridDim.x * (blockDim.x >> 5);
    float a0 = 0.f, a1 = 0.f;
    for (int e = blockIdx.x * (blockDim.x >> 5) + (threadIdx.x >> 5); e < EIc; e += nw) {
        int u = inter[e], it = inter[EIc + e];
        float coef = exv[e] / den[u] / fmaxf((float)cntUi[u], 1.f);
        const float* v = Vt + it * 64;
        a0 = fmaf(coef, v[lane], a0);
        a1 = fmaf(coef, v[lane + 32], a1);
    }
    atomicAdd(&sacc[lane], a0);
    atomicAdd(&sacc[lane + 32], a1);
    __syncthreads();
    if (threadIdx.x < 64) atomicAdd(&s[threadIdx.x], sacc[threadIdx.x]);
}

__global__ void cvec_kernel(const float* __restrict__ rtW2, const float* __restrict__ rtb2,
                            const float* __restrict__ sv, float* __restrict__ c) {
    __shared__ float ss[64];
    int i = threadIdx.x;
    if (i < 64) ss[i] = sv[i];
    __syncthreads();
    if (i < 64) {
        float acc = 0.f;
#pragma unroll
        for (int j = 0; j < 64; j++) acc = fmaf(rtW2[i * 64 + j], ss[j], acc);
        c[i] = acc;
        if (i == 0) {
            float d = 0.f;
            for (int j = 0; j < 64; j++) d = fmaf(rtb2[j], ss[j], d);
            c[64] = d;
        }
    }
}

// ---------------- factorized fact/router -> omega ----------------
__global__ __launch_bounds__(256) void fact2_kernel(
    const int* __restrict__ eidx, const int* __restrict__ etype,
    const float* __restrict__ P, const float* __restrict__ relA,
    const float* __restrict__ relB, const float* __restrict__ fpb1,
    const float* __restrict__ fpW2, const float* __restrict__ fpb2,
    const float* __restrict__ rtb1, const float* __restrict__ cvec,
    float* __restrict__ omega) {
    __shared__ float sA2[NREL * 64], sB2[NREL * 64];
    __shared__ float sb1[64], srb1[64], sc[64], sW2[192];
    __shared__ float sb2[3], sdc;
    for (int i = threadIdx.x; i < NREL * 64; i += blockDim.x) { sA2[i] = relA[i]; sB2[i] = relB[i]; }
    if (threadIdx.x < 64) {
        sb1[threadIdx.x] = fpb1[threadIdx.x];
        srb1[threadIdx.x] = rtb1[threadIdx.x];
        sc[threadIdx.x] = cvec[threadIdx.x];
    }
    if (threadIdx.x < 192) sW2[threadIdx.x] = fpW2[threadIdx.x];
    if (threadIdx.x < 3) sb2[threadIdx.x] = fpb2[threadIdx.x];
    if (threadIdx.x == 0) sdc = cvec[64];
    __syncthreads();

    int lane = threadIdx.x & 31;
    int nw = gridDim.x * (blockDim.x >> 5);
    for (int e = blockIdx.x * (blockDim.x >> 5) + (threadIdx.x >> 5); e < EK; e += nw) {
        int hh = eidx[e], tt = eidx[EK + e], rr = etype[e] - 1;
        const float2* Ph = (const float2*)(P + hh * 192);
        const float2* Pt = (const float2*)(P + tt * 192);
        float2 a1 = Ph[lane];
        float2 a3 = Pt[lane + 32];
        float2 b1h = Ph[lane + 64];
        float2 b1t = Pt[lane + 64];
        float2 a2 = *(const float2*)(sA2 + rr * 64 + 2 * lane);
        float hx = fsig(a1.x + a3.x + a2.x + sb1[2 * lane]);
        float hy = fsig(a1.y + a3.y + a2.y + sb1[2 * lane + 1]);
        float p0 = hx * sW2[(2 * lane) * 3 + 0] + hy * sW2[(2 * lane + 1) * 3 + 0];
        float p1 = hx * sW2[(2 * lane) * 3 + 1] + hy * sW2[(2 * lane + 1) * 3 + 1];
        float p2 = hx * sW2[(2 * lane) * 3 + 2] + hy * sW2[(2 * lane + 1) * 3 + 2];
#pragma unroll
        for (int o = 16; o; o >>= 1) {
            p0 += __shfl_xor_sync(0xffffffffu, p0, o);
            p1 += __shfl_xor_sync(0xffffffffu, p1, o);
            p2 += __shfl_xor_sync(0xffffffffu, p2, o);
        }
        p0 += sb2[0]; p1 += sb2[1]; p2 += sb2[2];
        float mx = fmaxf(p0, fmaxf(p1, p2));
        float e0 = __expf(p0 - mx), e1 = __expf(p1 - mx), e2 = __expf(p2 - mx);
        float inv = 1.f / (e0 + e1 + e2);
        float w0 = e0 * inv, w1 = e1 * inv, w2 = e2 * inv;
        float2 b2r = *(const float2*)(sB2 + rr * 64 + 2 * lane);
        float gx = fsig(w0 * b1h.x + w1 * b2r.x + w2 * b1t.x + srb1[2 * lane]);
        float gy = fsig(w0 * b1h.y + w1 * b2r.y + w2 * b1t.y + srb1[2 * lane + 1]);
        float pp = gx * sc[2 * lane] + gy * sc[2 * lane + 1];
#pragma unroll
        for (int o = 16; o; o >>= 1) pp += __shfl_xor_sync(0xffffffffu, pp, o);
        if (lane == 0) omega[e] = (pp + sdc) * 0.125f;
    }
}

// ---------------- per-head rho (alpha/eta) in CSR order ----------------
__global__ void rho_kernel(const int* __restrict__ offH, const int* __restrict__ cntHi,
                           const int* __restrict__ kg_eid, const float* __restrict__ omega,
                           float* __restrict__ rho_a, float* __restrict__ rho_e) {
    int n = blockIdx.x * 8 + (threadIdx.x >> 5);
    if (n >= NE) return;
    int lane = threadIdx.x & 31;
    int base = offH[n], end = base + cntHi[n];
    float sum = 0.f;
    for (int s = base + lane; s < end; s += 32) {
        float o = omega[kg_eid[s]];
        rho_a[s] = o;
        sum += o;
    }
#pragma unroll
    for (int o = 16; o; o >>= 1) sum += __shfl_xor_sync(0xffffffffu, sum, o);
    float segO = sum + 1e-8f;
    float esum = 0.f;
    for (int s = base + lane; s < end; s += 32) {
        float a = rho_a[s] / segO;
        rho_a[s] = a;
        float et = (a > 0.2f) ? a : 0.f;
        rho_e[s] = et;
        esum += et;
    }
#pragma unroll
    for (int o = 16; o; o >>= 1) esum += __shfl_xor_sync(0xffffffffu, esum, o);
    float segE = esum + 1e-8f;
    for (int s = base + lane; s < end; s += 32)
        rho_e[s] = rho_e[s] / segE;
}

// ---------------- hop: pure gather, warp per destination node ----------------
#define ENTB (NE / 8)
#define USRB (NU / 8)
__global__ __launch_bounds__(256) void hop_kernel(
    const float* __restrict__ eembOld, const int* __restrict__ offH,
    const int* __restrict__ cntHi, const int* __restrict__ kg_tr,
    const float* __restrict__ rhoArr, const float* __restrict__ relemb,
    float* __restrict__ eembNew, float* __restrict__ oute,
    const int* __restrict__ offU, const int* __restrict__ cntUi,
    const int* __restrict__ ui_item, const float* __restrict__ ui_w,
    float* __restrict__ outu) {
    __shared__ float srel[NREL * 64];
    int b = blockIdx.x;
    int lane = threadIdx.x & 31;
    int w = threadIdx.x >> 5;
    const float2* E2 = (const float2*)eembOld;
    if (b < ENTB) {
        for (int i = threadIdx.x; i < NREL * 64; i += blockDim.x) srel[i] = relemb[i];
        __syncthreads();
        int n = b * 8 + w;
        int base = offH[n], deg = cntHi[n];
        const float2* R2 = (const float2*)srel;
        float2 acc = make_float2(0.f, 0.f);
        for (int s = base; s < base + deg; s++) {
            int tr = kg_tr[s];
            float rho = rhoArr[s];
            float2 ev = E2[(tr >> 4) * 32 + lane];
            float2 rv = R2[(tr & 15) * 32 + lane];
            acc.x = fmaf(ev.x * rv.x, rho, acc.x);
            acc.y = fmaf(ev.y * rv.y, rho, acc.y);
        }
        float inv = 1.f / fmaxf((float)deg, 1.f);
        acc.x *= inv; acc.y *= inv;
        float ss = acc.x * acc.x + acc.y * acc.y;
#pragma unroll
        for (int o = 16; o; o >>= 1) ss += __shfl_xor_sync(0xffffffffu, ss, o);
        float invn = 1.f / fmaxf(sqrtf(ss), 1e-8f);
        float a = n2n(acc.x * invn), bb = n2n(acc.y * invn);
        *(float2*)(eembNew + n * 64 + 2 * lane) = make_float2(a, bb);
        float2 o2 = *(float2*)(oute + n * 64 + 2 * lane);
        o2.x += a; o2.y += bb;
        *(float2*)(oute + n * 64 + 2 * lane) = o2;
    } else {
        int n = (b - ENTB) * 8 + w;
        int base = offU[n], deg = cntUi[n];
        float2 acc = make_float2(0.f, 0.f);
        for (int s = base; s < base + deg; s++) {
            int it = ui_item[s];
            float ww = ui_w[s];
            float2 ev = E2[it * 32 + lane];
            acc.x = fmaf(ev.x, ww, acc.x);
            acc.y = fmaf(ev.y, ww, acc.y);
        }
        float ss = acc.x * acc.x + acc.y * acc.y;
#pragma unroll
        for (int o = 16; o; o >>= 1) ss += __shfl_xor_sync(0xffffffffu, ss, o);
        float invn = 1.f / fmaxf(sqrtf(ss), 1e-8f);
        float a = n2n(acc.x * invn), bb = n2n(acc.y * invn);
        float2 o2 = *(float2*)(outu + n * 64 + 2 * lane);
        o2.x += a; o2.y += bb;
        *(float2*)(outu + n * 64 + 2 * lane) = o2;
    }
}

// ---------------- host launch ----------------
extern "C" void kernel_launch(void* const* d_in, const int* in_sizes, int n_in,
                              void* d_out, int out_size) {
    const float* user_embed = (const float*)d_in[0];
    const float* item_embed = (const float*)d_in[1];
    const float* Wq = (const float*)d_in[2];
    const float* Wk = (const float*)d_in[3];
    const float* Wv = (const float*)d_in[4];
    const float* ent_real = (const float*)d_in[5];
    const float* ent_imag = (const float*)d_in[6];
    const float* rel_real = (const float*)d_in[7];
    const float* rel_imag = (const float*)d_in[8];
    const float* fp_W1 = (const float*)d_in[9];
    const float* fp_b1 = (const float*)d_in[10];
    const float* fp_W2 = (const float*)d_in[11];
    const float* fp_b2 = (const float*)d_in[12];
    const float* rt_W1 = (const float*)d_in[13];
    const float* rt_b1 = (const float*)d_in[14];
    const float* rt_W2 = (const float*)d_in[15];
    const float* rt_b2 = (const float*)d_in[16];
    const float* relation_emb = (const float*)d_in[17];
    const float* user_emb = (const float*)d_in[18];
    const float* entity_emb = (const float*)d_in[19];
    const float* inter_edge_w = (const float*)d_in[20];
    const int* edge_index = (const int*)d_in[21];
    const int* edge_type = (const int*)d_in[22];
    const int* inter_edge = (const int*)d_in[23];
    float* out = (float*)d_out;

    float *Qu, *Kt, *Vt, *scores, *smallf, *omega, *P, *relA, *relB;
    float *eembA, *eembB, *ui_w, *rho_a, *rho_e;
    int *smalli, *offH, *offU, *bsumH, *bsumU, *kg_tr, *kg_eid, *ui_item;
    cudaGetSymbolAddress((void**)&Qu, g_Qu);
    cudaGetSymbolAddress((void**)&Kt, g_Kt);
    cudaGetSymbolAddress((void**)&Vt, g_Vt);
    cudaGetSymbolAddress((void**)&scores, g_scores);
    cudaGetSymbolAddress((void**)&smallf, g_smallf);
    cudaGetSymbolAddress((void**)&smalli, g_smalli);
    cudaGetSymbolAddress((void**)&offH, g_offH);
    cudaGetSymbolAddress((void**)&offU, g_offU);
    cudaGetSymbolAddress((void**)&bsumH, g_bsumH);
    cudaGetSymbolAddress((void**)&bsumU, g_bsumU);
    cudaGetSymbolAddress((void**)&kg_tr, g_kg_tr);
    cudaGetSymbolAddress((void**)&kg_eid, g_kg_eid);
    cudaGetSymbolAddress((void**)&ui_item, g_ui_item);
    cudaGetSymbolAddress((void**)&ui_w, g_ui_w);
    cudaGetSymbolAddress((void**)&rho_a, g_rho_a);
    cudaGetSymbolAddress((void**)&rho_e, g_rho_e);
    cudaGetSymbolAddress((void**)&omega, g_omega);
    cudaGetSymbolAddress((void**)&P, g_P);
    cudaGetSymbolAddress((void**)&relA, g_relA);
    cudaGetSymbolAddress((void**)&relB, g_relB);
    cudaGetSymbolAddress((void**)&eembA, g_eembA);
    cudaGetSymbolAddress((void**)&eembB, g_eembB);

    unsigned* mkey = (unsigned*)(smallf + OFF_MKEY);
    float* den = smallf + OFF_DEN;
    float* sv = smallf + OFF_SV;
    float* cvec = smallf + OFF_C;
    int* cntHi = smalli + IOFF_CNTH;
    int* curH = smalli + IOFF_CURH;
    int* cntUi = smalli + IOFF_CNTU;
    int* curU = smalli + IOFF_CURU;

    cudaMemsetAsync(smallf, 0, SMALLF_TOT * sizeof(float));
    cudaMemsetAsync(smalli, 0, SMALLI_TOT * sizeof(int));

    // CSR build
    count_kernel<<<(EIc + 255) / 256, 256>>>(edge_index, inter_edge, cntHi, cntUi);
    {
        int nbH = (NE + 1023) / 1024;
        scan1_kernel<<<nbH, 1024>>>(cntHi, NE, offH, bsumH);
        scan2_kernel<<<1, 1024>>>(bsumH, nbH);
        scan3_kernel<<<nbH, 1024>>>(offH, bsumH, NE);
        int nbU = (NU + 1023) / 1024;
        scan1_kernel<<<nbU, 1024>>>(cntUi, NU, offU, bsumU);
        scan2_kernel<<<1, 1024>>>(bsumU, nbU);
        scan3_kernel<<<nbU, 1024>>>(offU, bsumU, NU);
    }
    fillKG_kernel<<<(EK + 255) / 256, 256>>>(edge_index, edge_type, offH, curH, kg_tr, kg_eid);
    fillUI_kernel<<<(EIc + 255) / 256, 256>>>(inter_edge, inter_edge_w, offU, curU, ui_item, ui_w);

    // precomputes
    precompP_kernel<<<1184, 256>>>(ent_real, ent_imag, fp_W1, rt_W1, P);
    relAB_kernel<<<(NREL * 64 + 255) / 256, 256>>>(rel_real, rel_imag, fp_W1, rt_W1, relA, relB);

    gemm64_kernel<<<(NU * 16 + 255) / 256, 256>>>(user_embed, Wq, Qu, NU);
    gemm64_kernel<<<(NI * 16 + 255) / 256, 256>>>(item_embed, Wk, Kt, NI);
    gemm64_kernel<<<(NI * 16 + 255) / 256, 256>>>(item_embed, Wv, Vt, NI);

    scores_kernel<<<(EIc / 2 + 7) / 8, 256>>>(Qu, Kt, inter_edge, inter_edge_w, scores, mkey);
    exp_kernel<<<(EIc + 255) / 256, 256>>>(inter_edge, scores, mkey, den);
    pref_kernel<<<512, 256>>>(Vt, inter_edge, scores, den, cntUi, sv);
    cvec_kernel<<<1, 64>>>(rt_W2, rt_b2, sv, cvec);

    fact2_kernel<<<1184, 256>>>(edge_index, edge_type, P, relA, relB, fp_b1, fp_W2, fp_b2,
                                rt_b1, cvec, omega);

    rho_kernel<<<(NE + 7) / 8, 256>>>(offH, cntHi, kg_eid, omega, rho_a, rho_e);

    cudaMemcpyAsync(eembA, entity_emb, (size_t)NE * DD * sizeof(float), cudaMemcpyDeviceToDevice);
    cudaMemcpyAsync(out, entity_emb, (size_t)NE * DD * sizeof(float), cudaMemcpyDeviceToDevice);
    cudaMemcpyAsync(out + (size_t)NE * DD, user_emb, (size_t)NU * DD * sizeof(float),
                    cudaMemcpyDeviceToDevice);

    float* outu = out + (size_t)NE * DD;
    // hop 1: A -> B (rho = alpha)
    hop_kernel<<<ENTB + USRB, 256>>>(eembA, offH, cntHi, kg_tr, rho_a, relation_emb,
                                     eembB, out, offU, cntUi, ui_item, ui_w, outu);
    // hop 2: B -> A (rho = alpha)
    hop_kernel<<<ENTB + USRB, 256>>>(eembB, offH, cntHi, kg_tr, rho_a, relation_emb,
                                     eembA, out, offU, cntUi, ui_item, ui_w, outu);
    // hop 3: A -> B (rho = eta)
    hop_kernel<<<ENTB + USRB, 256>>>(eembA, offH, cntHi, kg_tr, rho_e, relation_emb,
                                     eembB, out, offU, cntUi, ui_item, ui_w, outu);
}